// round 1
// baseline (speedup 1.0000x reference)
#include <cuda_runtime.h>
#include <math.h>
#include <float.h>

#define B 8
#define H 480
#define W 640
#define HW (H*W)
#define TOPK 500
#define NKP (B*TOPK)
#define CAP 131072

#define KXY_OFF 0
#define DESC_OFF (NKP*2)
#define KPS_OFF (DESC_OFF + NKP*64)
#define DISP_OFF (KPS_OFF + NKP)

// ---------------- device scratch (no allocations allowed) ----------------
__device__ unsigned char g_mm[B*HW];   // max mask
__device__ unsigned char g_sm[B*HW];   // suppression mask
__device__ float         g_ss[B*HW];   // suppressed scores
__device__ float         g_cval[B*CAP];
__device__ int           g_cidx[B*CAP];
__device__ int           g_cnt[B];
__device__ int           g_topk[NKP];
__device__ float         g_px[NKP];
__device__ float         g_py[NKP];

// tile constants for 5x5 window kernels: block 32x8, halo 2
#define TW 36
#define TH 12

__global__ void zero_cnt_kernel() {
    if (threadIdx.x < B) g_cnt[threadIdx.x] = 0;
}

// mm = (s == maxpool5x5(s))   (OOB treated as 0; safe since s >= 0 and window contains center)
__global__ void mask_kernel(const float* __restrict__ s) {
    __shared__ float t[TH*TW];
    int b = blockIdx.z;
    const float* sp = s + (size_t)b*HW;
    int tid = threadIdx.y*32 + threadIdx.x;
    int gx0 = blockIdx.x*32 - 2, gy0 = blockIdx.y*8 - 2;
    for (int i = tid; i < TH*TW; i += 256) {
        int r = i / TW, c = i % TW;
        int gy = gy0 + r, gx = gx0 + c;
        t[i] = (gy >= 0 && gy < H && gx >= 0 && gx < W) ? sp[gy*W + gx] : 0.f;
    }
    __syncthreads();
    float m = -FLT_MAX;
    #pragma unroll
    for (int dy = 0; dy < 5; dy++)
        #pragma unroll
        for (int dx = 0; dx < 5; dx++)
            m = fmaxf(m, t[(threadIdx.y+dy)*TW + threadIdx.x+dx]);
    float v = t[(threadIdx.y+2)*TW + threadIdx.x+2];
    int x = blockIdx.x*32 + threadIdx.x;
    int y = blockIdx.y*8 + threadIdx.y;
    g_mm[(size_t)b*HW + y*W + x] = (v == m) ? 1 : 0;
}

// sm = maxpool5x5(mm) > 0 ;  ss = sm ? 0 : s
__global__ void supp_kernel(const float* __restrict__ s) {
    __shared__ unsigned char t[TH*TW];
    int b = blockIdx.z;
    const unsigned char* mp = g_mm + (size_t)b*HW;
    int tid = threadIdx.y*32 + threadIdx.x;
    int gx0 = blockIdx.x*32 - 2, gy0 = blockIdx.y*8 - 2;
    for (int i = tid; i < TH*TW; i += 256) {
        int r = i / TW, c = i % TW;
        int gy = gy0 + r, gx = gx0 + c;
        t[i] = (gy >= 0 && gy < H && gx >= 0 && gx < W) ? mp[gy*W + gx] : 0;
    }
    __syncthreads();
    int any = 0;
    #pragma unroll
    for (int dy = 0; dy < 5; dy++)
        #pragma unroll
        for (int dx = 0; dx < 5; dx++)
            any |= t[(threadIdx.y+dy)*TW + threadIdx.x+dx];
    int x = blockIdx.x*32 + threadIdx.x;
    int y = blockIdx.y*8 + threadIdx.y;
    size_t p = (size_t)b*HW + y*W + x;
    g_sm[p] = any ? 1 : 0;
    g_ss[p] = any ? 0.f : s[p];
}

// nm = (ss == maxpool5x5(ss)) ; mm |= nm & !sm
__global__ void update_kernel() {
    __shared__ float t[TH*TW];
    int b = blockIdx.z;
    const float* sp = g_ss + (size_t)b*HW;
    int tid = threadIdx.y*32 + threadIdx.x;
    int gx0 = blockIdx.x*32 - 2, gy0 = blockIdx.y*8 - 2;
    for (int i = tid; i < TH*TW; i += 256) {
        int r = i / TW, c = i % TW;
        int gy = gy0 + r, gx = gx0 + c;
        t[i] = (gy >= 0 && gy < H && gx >= 0 && gx < W) ? sp[gy*W + gx] : 0.f;
    }
    __syncthreads();
    float m = -FLT_MAX;
    #pragma unroll
    for (int dy = 0; dy < 5; dy++)
        #pragma unroll
        for (int dx = 0; dx < 5; dx++)
            m = fmaxf(m, t[(threadIdx.y+dy)*TW + threadIdx.x+dx]);
    float v = t[(threadIdx.y+2)*TW + threadIdx.x+2];
    int x = blockIdx.x*32 + threadIdx.x;
    int y = blockIdx.y*8 + threadIdx.y;
    size_t p = (size_t)b*HW + y*W + x;
    int nm = (v == m) && !g_sm[p];
    if (nm) g_mm[p] = 1;
}

// candidate compaction: mask positions inside valid border
__global__ void compact_kernel(const float* __restrict__ s) {
    for (int i = blockIdx.x*blockDim.x + threadIdx.x; i < B*HW; i += gridDim.x*blockDim.x) {
        if (!g_mm[i]) continue;
        int b = i / HW;
        int p = i - b*HW;
        int y = p / W, x = p - y*W;
        if (y < 3 || y >= H-2 || x < 3 || x >= W-2) continue;
        int pos = atomicAdd(&g_cnt[b], 1);
        if (pos < CAP) {
            g_cval[b*CAP + pos] = s[i];
            g_cidx[b*CAP + pos] = p;
        }
    }
}

// per-batch top-500: 3-level radix histogram threshold + bitonic sort of survivors
__global__ void select_kernel() {
    __shared__ unsigned hist[2048];
    __shared__ unsigned sel_key[1024];
    __shared__ int      sel_idx[1024];
    __shared__ int s_bsel, s_need, s_cnt;

    int b = blockIdx.x;
    int tid = threadIdx.x;
    int n = min(g_cnt[b], CAP);
    const float* vals = g_cval + b*CAP;
    const int*   idxs = g_cidx + b*CAP;

    unsigned prefix = 0;
    int need = TOPK;
    // level 0: bits [31:21] (11b); level 1: bits [20:10] (11b); level 2: bits [9:0] (10b)
    for (int level = 0; level < 3; level++) {
        int nbins = (level == 2) ? 1024 : 2048;
        for (int i = tid; i < 2048; i += 1024) hist[i] = 0;
        __syncthreads();
        for (int i = tid; i < n; i += 1024) {
            unsigned key = __float_as_uint(vals[i]);
            unsigned bin;
            bool ok;
            if (level == 0)      { ok = true;                    bin = key >> 21; }
            else if (level == 1) { ok = (key >> 21) == prefix;   bin = (key >> 10) & 0x7FF; }
            else                 { ok = (key >> 10) == prefix;   bin = key & 0x3FF; }
            if (ok) atomicAdd(&hist[bin], 1);
        }
        __syncthreads();
        if (tid == 0) {
            int cum = 0, bsel = 0, nneed = need;
            for (int bin = nbins - 1; bin >= 0; bin--) {
                int c = (int)hist[bin];
                if (cum + c >= need) { bsel = bin; nneed = need - cum; break; }
                cum += c;
            }
            s_bsel = bsel; s_need = nneed;
        }
        __syncthreads();
        if (level == 0)      prefix = (unsigned)s_bsel;
        else if (level == 1) prefix = (prefix << 11) | (unsigned)s_bsel;
        else                 prefix = (prefix << 10) | (unsigned)s_bsel;
        need = s_need;
        __syncthreads();
    }
    unsigned T = prefix;   // exact 500th-largest key

    if (tid == 0) s_cnt = 0;
    __syncthreads();
    for (int i = tid; i < n; i += 1024) {
        unsigned key = __float_as_uint(vals[i]);
        if (key >= T) {
            int p = atomicAdd(&s_cnt, 1);
            if (p < 1024) { sel_key[p] = key; sel_idx[p] = idxs[i]; }
        }
    }
    __syncthreads();
    int cnt = min(s_cnt, 1024);
    if (tid >= cnt) { sel_key[tid] = 0; sel_idx[tid] = 0x7FFFFFFF; }
    __syncthreads();

    // bitonic sort, descending key, ascending index on ties (matches lax.top_k)
    for (int k = 2; k <= 1024; k <<= 1) {
        for (int j = k >> 1; j > 0; j >>= 1) {
            int i = tid, ixj = i ^ j;
            if (ixj > i) {
                unsigned ka = sel_key[i], kb = sel_key[ixj];
                int ia = sel_idx[i], ib = sel_idx[ixj];
                bool a_first = (ka > kb) || (ka == kb && ia < ib);
                bool dir = ((i & k) == 0);     // true: want a before b
                if (a_first != dir) {
                    sel_key[i] = kb; sel_key[ixj] = ka;
                    sel_idx[i] = ib; sel_idx[ixj] = ia;
                }
            }
            __syncthreads();
        }
    }
    if (tid < TOPK) g_topk[b*TOPK + tid] = sel_idx[tid];
}

__device__ __forceinline__ float wmax(float v) {
    #pragma unroll
    for (int o = 16; o > 0; o >>= 1) v = fmaxf(v, __shfl_xor_sync(0xffffffffu, v, o));
    return v;
}
__device__ __forceinline__ float wsum(float v) {
    #pragma unroll
    for (int o = 16; o > 0; o >>= 1) v += __shfl_xor_sync(0xffffffffu, v, o);
    return v;
}

// one warp per keypoint: 5x5 patch softmax refinement, disp, kxy, kptscore
__global__ void patch_kernel(const float* __restrict__ s, float* __restrict__ out) {
    int gw = blockIdx.x * (blockDim.x >> 5) + (threadIdx.x >> 5);
    if (gw >= NKP) return;
    int lane = threadIdx.x & 31;
    int b = gw / TOPK;
    int p = g_topk[gw];
    int y = p / W, x = p - y*W;

    int ky = lane / 5, kx = lane - ky*5;
    float v = -FLT_MAX;
    if (lane < 25) v = s[(size_t)b*HW + (y + ky - 2)*W + (x + kx - 2)];
    float mx = wmax(v);
    float e = (lane < 25) ? expf((v - mx) / 0.1f) : 0.f;
    float ssum = wsum(e);
    float gxk = (float)(kx - 2), gyk = (float)(ky - 2);
    float sx = wsum(e * gxk);
    float sy = wsum(e * gyk);
    float denom = ssum + 1e-12f;
    float xr = sx / denom, yr = sy / denom;
    float dx = (gxk - xr) * 0.5f, dy = (gyk - yr) * 0.5f;
    float disp = wsum(e * (dx*dx + dy*dy)) / denom;

    if (lane == 0) {
        float fx = (float)x + xr, fy = (float)y + yr;
        float gx = fx / (float)(W-1) * 2.f - 1.f;
        float gy = fy / (float)(H-1) * 2.f - 1.f;
        out[KXY_OFF + gw*2 + 0] = gx;
        out[KXY_OFF + gw*2 + 1] = gy;
        out[DISP_OFF + gw] = disp;

        float px = fminf(fmaxf((gx + 1.f) * 0.5f * (float)(W-1), 0.f), (float)(W-1));
        float py = fminf(fmaxf((gy + 1.f) * 0.5f * (float)(H-1), 0.f), (float)(H-1));
        g_px[gw] = px; g_py[gw] = py;
        int x0 = (int)floorf(px), y0 = (int)floorf(py);
        float wx = px - (float)x0, wy = py - (float)y0;
        int x1 = min(x0 + 1, W-1), y1 = min(y0 + 1, H-1);
        const float* sb = s + (size_t)b*HW;
        float v00 = sb[y0*W + x0], v01 = sb[y0*W + x1];
        float v10 = sb[y1*W + x0], v11 = sb[y1*W + x1];
        out[KPS_OFF + gw] = v00*(1.f-wx)*(1.f-wy) + v01*wx*(1.f-wy)
                          + v10*(1.f-wx)*wy       + v11*wx*wy;
    }
}

// 64 threads per keypoint: descriptor bilinear gather + L2 normalize
__global__ void desc_kernel(const float* __restrict__ dmap, float* __restrict__ out) {
    int g = blockIdx.x * 4 + (threadIdx.x >> 6);
    int c = threadIdx.x & 63;
    if (g >= NKP) return;
    float px = g_px[g], py = g_py[g];
    int x0 = (int)floorf(px), y0 = (int)floorf(py);
    float wx = px - (float)x0, wy = py - (float)y0;
    int x1 = min(x0 + 1, W-1), y1 = min(y0 + 1, H-1);
    int b = g / TOPK;
    const float* base = dmap + ((size_t)b*64 + c) * (size_t)HW;
    float v00 = base[y0*W + x0], v01 = base[y0*W + x1];
    float v10 = base[y1*W + x0], v11 = base[y1*W + x1];
    float d = v00*(1.f-wx)*(1.f-wy) + v01*wx*(1.f-wy)
            + v10*(1.f-wx)*wy       + v11*wx*wy;

    float ss = d * d;
    #pragma unroll
    for (int o = 16; o > 0; o >>= 1) ss += __shfl_xor_sync(0xffffffffu, ss, o);
    __shared__ float part[8];
    int wid = threadIdx.x >> 5;
    if ((threadIdx.x & 31) == 0) part[wid] = ss;
    __syncthreads();
    int gl = threadIdx.x >> 6;
    float tot = part[2*gl] + part[2*gl + 1];
    float nrm = fmaxf(sqrtf(tot), 1e-12f);
    out[DESC_OFF + g*64 + c] = d / nrm;
}

extern "C" void kernel_launch(void* const* d_in, const int* in_sizes, int n_in,
                              void* d_out, int out_size) {
    const float* scores = (const float*)d_in[0];
    const float* descs  = (const float*)d_in[1];
    float* out = (float*)d_out;

    dim3 blk(32, 8);
    dim3 grd(W/32, H/8, B);

    zero_cnt_kernel<<<1, 32>>>();
    mask_kernel<<<grd, blk>>>(scores);
    supp_kernel<<<grd, blk>>>(scores);
    update_kernel<<<grd, blk>>>();
    supp_kernel<<<grd, blk>>>(scores);
    update_kernel<<<grd, blk>>>();
    compact_kernel<<<2400, 512>>>(scores);
    select_kernel<<<B, 1024>>>();
    patch_kernel<<<(NKP*32 + 255)/256, 256>>>(scores, out);
    desc_kernel<<<NKP/4, 256>>>(descs, out);
}

// round 2
// speedup vs baseline: 4.7652x; 4.7652x over previous
#include <cuda_runtime.h>
#include <math.h>
#include <float.h>

#define B 8
#define H 480
#define W 640
#define HW (H*W)
#define TOPK 500
#define NKP (B*TOPK)
#define CAP 131072

#define KXY_OFF 0
#define DESC_OFF (NKP*2)
#define KPS_OFF (DESC_OFF + NKP*64)
#define DISP_OFF (KPS_OFF + NKP)

// ---------------- device scratch (no allocations allowed) ----------------
__device__ float g_cval[B*CAP];
__device__ int   g_cidx[B*CAP];
__device__ int   g_cnt[B];
__device__ int   g_topk[NKP];
__device__ float g_px[NKP];
__device__ float g_py[NKP];

__global__ void zero_cnt_kernel() {
    if (threadIdx.x < B) g_cnt[threadIdx.x] = 0;
}

// ============================================================================
// Fused NMS: entire 5-stage modified-NMS + border mask + candidate compaction
// in one kernel. 32x32 output tile, radius-10 halo -> 52x52 smem tile.
// All maxpools separable (vertical then horizontal), masks as uchar.
// ============================================================================
#define TS 52

__device__ __forceinline__ float fmax5(float a, float b, float c, float d, float e) {
    return fmaxf(fmaxf(fmaxf(a, b), fmaxf(c, d)), e);
}

__global__ __launch_bounds__(256) void nms_kernel(const float* __restrict__ s) {
    __shared__ float sT[TS*TS];     // scores tile (const after load)
    __shared__ float SS[TS*TS];     // suppressed scores
    __shared__ float TMPF[TS*TS];   // float vpass temp
    __shared__ unsigned char M[TS*TS];    // max mask
    __shared__ unsigned char SM[TS*TS];   // supp mask
    __shared__ unsigned char TMPU[TS*TS]; // uchar vpass temp

    int b = blockIdx.z;
    int tid = threadIdx.x;
    int gx0 = blockIdx.x*32 - 10, gy0 = blockIdx.y*32 - 10;
    const float* sp = s + (size_t)b*HW;

    // load tile (OOB = 0; equivalent to -inf padding since scores >= 0)
    for (int i = tid; i < TS*TS; i += 256) {
        int r = i / TS, c = i - r*TS;
        int gy = gy0 + r, gx = gx0 + c;
        sT[i] = (gy >= 0 && gy < H && gx >= 0 && gx < W) ? sp[gy*W + gx] : 0.f;
    }
    __syncthreads();

    // ---- stage 1: M = (s == max5(s)) on [2,50)^2 ----
    for (int i = tid; i < 48*52; i += 256) {
        int r = 2 + i/52, c = i - (i/52)*52;
        TMPF[r*TS+c] = fmax5(sT[(r-2)*TS+c], sT[(r-1)*TS+c], sT[r*TS+c],
                             sT[(r+1)*TS+c], sT[(r+2)*TS+c]);
    }
    __syncthreads();
    for (int i = tid; i < 48*48; i += 256) {
        int r = 2 + i/48, c = 2 + i - (i/48)*48;
        float v = fmax5(TMPF[r*TS+c-2], TMPF[r*TS+c-1], TMPF[r*TS+c],
                        TMPF[r*TS+c+1], TMPF[r*TS+c+2]);
        M[r*TS+c] = (sT[r*TS+c] == v) ? 1 : 0;
    }
    __syncthreads();

    // ---- stage 2: SM = max5(M)>0 on [4,48)^2 ; SS = SM ? 0 : s ----
    for (int i = tid; i < 44*48; i += 256) {
        int r = 4 + i/48, c = 2 + i - (i/48)*48;
        TMPU[r*TS+c] = M[(r-2)*TS+c] | M[(r-1)*TS+c] | M[r*TS+c]
                     | M[(r+1)*TS+c] | M[(r+2)*TS+c];
    }
    __syncthreads();
    for (int i = tid; i < 44*44; i += 256) {
        int r = 4 + i/44, c = 4 + i - (i/44)*44;
        int any = TMPU[r*TS+c-2] | TMPU[r*TS+c-1] | TMPU[r*TS+c]
                | TMPU[r*TS+c+1] | TMPU[r*TS+c+2];
        SM[r*TS+c] = any ? 1 : 0;
        SS[r*TS+c] = any ? 0.f : sT[r*TS+c];
    }
    __syncthreads();

    // ---- stage 3: M |= (SS == max5(SS)) & !SM on [6,46)^2 ----
    for (int i = tid; i < 40*44; i += 256) {
        int r = 6 + i/44, c = 4 + i - (i/44)*44;
        TMPF[r*TS+c] = fmax5(SS[(r-2)*TS+c], SS[(r-1)*TS+c], SS[r*TS+c],
                             SS[(r+1)*TS+c], SS[(r+2)*TS+c]);
    }
    __syncthreads();
    for (int i = tid; i < 40*40; i += 256) {
        int r = 6 + i/40, c = 6 + i - (i/40)*40;
        float v = fmax5(TMPF[r*TS+c-2], TMPF[r*TS+c-1], TMPF[r*TS+c],
                        TMPF[r*TS+c+1], TMPF[r*TS+c+2]);
        if (SS[r*TS+c] == v && !SM[r*TS+c]) M[r*TS+c] = 1;
    }
    __syncthreads();

    // ---- stage 4: SM = max5(M)>0 on [8,44)^2 ; SS = SM ? 0 : s ----
    for (int i = tid; i < 36*40; i += 256) {
        int r = 8 + i/40, c = 6 + i - (i/40)*40;
        TMPU[r*TS+c] = M[(r-2)*TS+c] | M[(r-1)*TS+c] | M[r*TS+c]
                     | M[(r+1)*TS+c] | M[(r+2)*TS+c];
    }
    __syncthreads();
    for (int i = tid; i < 36*36; i += 256) {
        int r = 8 + i/36, c = 8 + i - (i/36)*36;
        int any = TMPU[r*TS+c-2] | TMPU[r*TS+c-1] | TMPU[r*TS+c]
                | TMPU[r*TS+c+1] | TMPU[r*TS+c+2];
        SM[r*TS+c] = any ? 1 : 0;
        SS[r*TS+c] = any ? 0.f : sT[r*TS+c];
    }
    __syncthreads();

    // ---- stage 5 + border + compaction: final mask on [10,42)^2 ----
    for (int i = tid; i < 32*36; i += 256) {
        int r = 10 + i/36, c = 8 + i - (i/36)*36;
        TMPF[r*TS+c] = fmax5(SS[(r-2)*TS+c], SS[(r-1)*TS+c], SS[r*TS+c],
                             SS[(r+1)*TS+c], SS[(r+2)*TS+c]);
    }
    __syncthreads();
    for (int i = tid; i < 32*32; i += 256) {
        int r = 10 + i/32, c = 10 + i - (i/32)*32;
        float v = fmax5(TMPF[r*TS+c-2], TMPF[r*TS+c-1], TMPF[r*TS+c],
                        TMPF[r*TS+c+1], TMPF[r*TS+c+2]);
        int fin = M[r*TS+c] | ((SS[r*TS+c] == v) && !SM[r*TS+c]);
        if (fin) {
            int gy = gy0 + r, gx = gx0 + c;
            if (gy >= 3 && gy < H-2 && gx >= 3 && gx < W-2) {
                int pos = atomicAdd(&g_cnt[b], 1);
                if (pos < CAP) {
                    g_cval[b*CAP + pos] = sT[r*TS+c];
                    g_cidx[b*CAP + pos] = gy*W + gx;
                }
            }
        }
    }
}

// ============================================================================
// per-batch top-500: 3-level radix threshold (parallel suffix scan) + bitonic
// ============================================================================
__global__ __launch_bounds__(1024) void select_kernel() {
    __shared__ unsigned hist[2048];
    __shared__ unsigned hist2[2048];
    __shared__ unsigned sel_key[1024];
    __shared__ int      sel_idx[1024];
    __shared__ int s_bsel, s_need, s_cnt;

    int b = blockIdx.x;
    int tid = threadIdx.x;
    int n = min(g_cnt[b], CAP);
    const float* vals = g_cval + b*CAP;
    const int*   idxs = g_cidx + b*CAP;

    unsigned prefix = 0;
    int need = TOPK;
    for (int level = 0; level < 3; level++) {
        int nbins = (level == 2) ? 1024 : 2048;
        for (int i = tid; i < 2048; i += 1024) hist[i] = 0;
        if (tid == 0) { s_bsel = 0; s_need = need; }
        __syncthreads();
        for (int i = tid; i < n; i += 1024) {
            unsigned key = __float_as_uint(vals[i]);
            unsigned bin; bool ok;
            if (level == 0)      { ok = true;                  bin = key >> 21; }
            else if (level == 1) { ok = (key >> 21) == prefix; bin = (key >> 10) & 0x7FF; }
            else                 { ok = (key >> 10) == prefix; bin = key & 0x3FF; }
            if (ok) atomicAdd(&hist[bin], 1);
        }
        __syncthreads();
        // parallel inclusive suffix scan: src[i] = sum_{j>=i} hist[j]
        unsigned* src = hist;
        unsigned* dst = hist2;
        for (int d = 1; d < nbins; d <<= 1) {
            for (int i = tid; i < nbins; i += 1024)
                dst[i] = src[i] + ((i + d < nbins) ? src[i + d] : 0u);
            __syncthreads();
            unsigned* t = src; src = dst; dst = t;
        }
        for (int i = tid; i < nbins; i += 1024) {
            if ((int)src[i] >= need && (i == nbins-1 || (int)src[i+1] < need)) {
                s_bsel = i;
                s_need = need - ((i == nbins-1) ? 0 : (int)src[i+1]);
            }
        }
        __syncthreads();
        if (level == 0)      prefix = (unsigned)s_bsel;
        else if (level == 1) prefix = (prefix << 11) | (unsigned)s_bsel;
        else                 prefix = (prefix << 10) | (unsigned)s_bsel;
        need = s_need;
        __syncthreads();
    }
    unsigned T = prefix;   // exact 500th-largest key

    if (tid == 0) s_cnt = 0;
    __syncthreads();
    for (int i = tid; i < n; i += 1024) {
        unsigned key = __float_as_uint(vals[i]);
        if (key >= T) {
            int p = atomicAdd(&s_cnt, 1);
            if (p < 1024) { sel_key[p] = key; sel_idx[p] = idxs[i]; }
        }
    }
    __syncthreads();
    int cnt = min(s_cnt, 1024);
    if (tid >= cnt) { sel_key[tid] = 0; sel_idx[tid] = 0x7FFFFFFF; }
    __syncthreads();

    // bitonic sort: descending key, ascending index on ties (lax.top_k order)
    for (int k = 2; k <= 1024; k <<= 1) {
        for (int j = k >> 1; j > 0; j >>= 1) {
            int i = tid, ixj = i ^ j;
            if (ixj > i) {
                unsigned ka = sel_key[i], kb = sel_key[ixj];
                int ia = sel_idx[i], ib = sel_idx[ixj];
                bool a_first = (ka > kb) || (ka == kb && ia < ib);
                bool dir = ((i & k) == 0);
                if (a_first != dir) {
                    sel_key[i] = kb; sel_key[ixj] = ka;
                    sel_idx[i] = ib; sel_idx[ixj] = ia;
                }
            }
            __syncthreads();
        }
    }
    if (tid < TOPK) g_topk[b*TOPK + tid] = sel_idx[tid];
}

__device__ __forceinline__ float wmax(float v) {
    #pragma unroll
    for (int o = 16; o > 0; o >>= 1) v = fmaxf(v, __shfl_xor_sync(0xffffffffu, v, o));
    return v;
}
__device__ __forceinline__ float wsum(float v) {
    #pragma unroll
    for (int o = 16; o > 0; o >>= 1) v += __shfl_xor_sync(0xffffffffu, v, o);
    return v;
}

// one warp per keypoint: 5x5 patch softmax refinement, disp, kxy, kptscore
__global__ void patch_kernel(const float* __restrict__ s, float* __restrict__ out) {
    int gw = blockIdx.x * (blockDim.x >> 5) + (threadIdx.x >> 5);
    if (gw >= NKP) return;
    int lane = threadIdx.x & 31;
    int b = gw / TOPK;
    int p = g_topk[gw];
    int y = p / W, x = p - y*W;

    int ky = lane / 5, kx = lane - ky*5;
    float v = -FLT_MAX;
    if (lane < 25) v = s[(size_t)b*HW + (y + ky - 2)*W + (x + kx - 2)];
    float mx = wmax(v);
    float e = (lane < 25) ? expf((v - mx) / 0.1f) : 0.f;
    float ssum = wsum(e);
    float gxk = (float)(kx - 2), gyk = (float)(ky - 2);
    float sx = wsum(e * gxk);
    float sy = wsum(e * gyk);
    float denom = ssum + 1e-12f;
    float xr = sx / denom, yr = sy / denom;
    float dx = (gxk - xr) * 0.5f, dy = (gyk - yr) * 0.5f;
    float disp = wsum(e * (dx*dx + dy*dy)) / denom;

    if (lane == 0) {
        float fx = (float)x + xr, fy = (float)y + yr;
        float gx = fx / (float)(W-1) * 2.f - 1.f;
        float gy = fy / (float)(H-1) * 2.f - 1.f;
        out[KXY_OFF + gw*2 + 0] = gx;
        out[KXY_OFF + gw*2 + 1] = gy;
        out[DISP_OFF + gw] = disp;

        float px = fminf(fmaxf((gx + 1.f) * 0.5f * (float)(W-1), 0.f), (float)(W-1));
        float py = fminf(fmaxf((gy + 1.f) * 0.5f * (float)(H-1), 0.f), (float)(H-1));
        g_px[gw] = px; g_py[gw] = py;
        int x0 = (int)floorf(px), y0 = (int)floorf(py);
        float wx = px - (float)x0, wy = py - (float)y0;
        int x1 = min(x0 + 1, W-1), y1 = min(y0 + 1, H-1);
        const float* sb = s + (size_t)b*HW;
        float v00 = sb[y0*W + x0], v01 = sb[y0*W + x1];
        float v10 = sb[y1*W + x0], v11 = sb[y1*W + x1];
        out[KPS_OFF + gw] = v00*(1.f-wx)*(1.f-wy) + v01*wx*(1.f-wy)
                          + v10*(1.f-wx)*wy       + v11*wx*wy;
    }
}

// 64 threads per keypoint: descriptor bilinear gather + L2 normalize
__global__ void desc_kernel(const float* __restrict__ dmap, float* __restrict__ out) {
    int g = blockIdx.x * 4 + (threadIdx.x >> 6);
    int c = threadIdx.x & 63;
    if (g >= NKP) return;
    float px = g_px[g], py = g_py[g];
    int x0 = (int)floorf(px), y0 = (int)floorf(py);
    float wx = px - (float)x0, wy = py - (float)y0;
    int x1 = min(x0 + 1, W-1), y1 = min(y0 + 1, H-1);
    int b = g / TOPK;
    const float* base = dmap + ((size_t)b*64 + c) * (size_t)HW;
    float v00 = base[y0*W + x0], v01 = base[y0*W + x1];
    float v10 = base[y1*W + x0], v11 = base[y1*W + x1];
    float d = v00*(1.f-wx)*(1.f-wy) + v01*wx*(1.f-wy)
            + v10*(1.f-wx)*wy       + v11*wx*wy;

    float ss = d * d;
    #pragma unroll
    for (int o = 16; o > 0; o >>= 1) ss += __shfl_xor_sync(0xffffffffu, ss, o);
    __shared__ float part[8];
    int wid = threadIdx.x >> 5;
    if ((threadIdx.x & 31) == 0) part[wid] = ss;
    __syncthreads();
    int gl = threadIdx.x >> 6;
    float tot = part[2*gl] + part[2*gl + 1];
    float nrm = fmaxf(sqrtf(tot), 1e-12f);
    out[DESC_OFF + g*64 + c] = d / nrm;
}

extern "C" void kernel_launch(void* const* d_in, const int* in_sizes, int n_in,
                              void* d_out, int out_size) {
    const float* scores = (const float*)d_in[0];
    const float* descs  = (const float*)d_in[1];
    float* out = (float*)d_out;

    zero_cnt_kernel<<<1, 32>>>();
    nms_kernel<<<dim3(W/32, H/32, B), 256>>>(scores);
    select_kernel<<<B, 1024>>>();
    patch_kernel<<<(NKP*32 + 255)/256, 256>>>(scores, out);
    desc_kernel<<<NKP/4, 256>>>(descs, out);
}

// round 3
// speedup vs baseline: 4.9854x; 1.0462x over previous
#include <cuda_runtime.h>
#include <math.h>
#include <float.h>

#define B 8
#define H 480
#define W 640
#define HW (H*W)
#define TOPK 500
#define NKP (B*TOPK)
#define CAP 131072

#define KXY_OFF 0
#define DESC_OFF (NKP*2)
#define KPS_OFF (DESC_OFF + NKP*64)
#define DISP_OFF (KPS_OFF + NKP)

// ---------------- device scratch ----------------
__device__ float g_cval[B*CAP];
__device__ int   g_cidx[B*CAP];
__device__ int   g_cnt[B];
__device__ int   g_topk[NKP];
__device__ float g_px[NKP];
__device__ float g_py[NKP];

__global__ void zero_cnt_kernel() {
    if (threadIdx.x < B) g_cnt[threadIdx.x] = 0;
}

// ============================================================================
// Fused NMS, vectorized: 32x32 tile + radius-10 halo -> 52 rows x 56 padded
// cols in smem (tile col c lives at smem col sc = c+2). All passes process
// 4-wide aligned chunks: float4 for scores, packed bytes-in-uint for masks.
// ============================================================================
#define WP 56

__device__ __forceinline__ float4 f4max(float4 a, float4 b) {
    return make_float4(fmaxf(a.x,b.x), fmaxf(a.y,b.y), fmaxf(a.z,b.z), fmaxf(a.w,b.w));
}
__device__ __forceinline__ float fmax5(float a, float b, float c, float d, float e) {
    return fmaxf(fmaxf(fmaxf(a, b), fmaxf(c, d)), e);
}

__global__ __launch_bounds__(256) void nms_kernel(const float* __restrict__ s) {
    __shared__ __align__(16) float sT[52*WP];
    __shared__ __align__(16) float SS[52*WP];
    __shared__ __align__(16) float TF[52*WP];
    __shared__ __align__(4) unsigned char M  [52*WP];
    __shared__ __align__(4) unsigned char SMK[52*WP];
    __shared__ __align__(4) unsigned char TU [52*WP];

    int b = blockIdx.z, tid = threadIdx.x;
    int gx0 = blockIdx.x*32 - 10, gy0 = blockIdx.y*32 - 10;
    const float* sp = s + (size_t)b*HW;

    for (int i = tid; i < 52*WP; i += 256) {
        int r = i / WP, sc = i - r*WP;
        int gy = gy0 + r, gx = gx0 + sc - 2;
        sT[i] = (gy >= 0 && gy < H && gx >= 0 && gx < W) ? sp[gy*W + gx] : 0.f;
    }
    __syncthreads();

#define F4(A, r, cb)  (*(const float4*)&A[(r)*WP + (cb)])
#define F4W(A, r, cb) (*(float4*)&A[(r)*WP + (cb)])
#define U32(A, r, cb)  (*(const unsigned*)&A[(r)*WP + (cb)])
#define U32W(A, r, cb) (*(unsigned*)&A[(r)*WP + (cb)])

    // vertical float max into TF from SRC over rows r-2..r+2
#define VPASS_F(SRC, R0, NR, CB0, NC)                                         \
    for (int i = tid; i < (NR)*(NC); i += 256) {                              \
        int q = i/(NC); int r = (R0)+q; int cb = (CB0) + 4*(i - q*(NC));      \
        float4 v = f4max(f4max(F4(SRC,r-2,cb), F4(SRC,r-1,cb)),               \
                         f4max(F4(SRC,r+1,cb), F4(SRC,r+2,cb)));              \
        F4W(TF,r,cb) = f4max(v, F4(SRC,r,cb));                                \
    }

    // horizontal 5-max of TF -> (o0..o3) at columns cb..cb+3
#define HWIN(r, cb, o0, o1, o2, o3)                                           \
    float4 L = F4(TF,r,cb-4), Md = F4(TF,r,cb), R = F4(TF,r,cb+4);            \
    float o0 = fmax5(L.z, L.w, Md.x, Md.y, Md.z);                             \
    float o1 = fmax5(L.w, Md.x, Md.y, Md.z, Md.w);                            \
    float o2 = fmax5(Md.x, Md.y, Md.z, Md.w, R.x);                            \
    float o3 = fmax5(Md.y, Md.z, Md.w, R.x, R.y);

    // ---- stage 1: M = (s == max5(s)) ----
    VPASS_F(sT, 2, 48, 0, 14)                       // TF rows [2,50), sc 0..55
    __syncthreads();
    for (int i = tid; i < 48*12; i += 256) {        // M rows [2,50), sc [4,52)
        int q = i/12; int r = 2+q; int cb = 4 + 4*(i - q*12);
        HWIN(r, cb, o0, o1, o2, o3)
        float4 t = F4(sT,r,cb);
        unsigned m = (t.x==o0 ? 1u:0u) | (t.y==o1 ? 0x100u:0u)
                   | (t.z==o2 ? 0x10000u:0u) | (t.w==o3 ? 0x1000000u:0u);
        U32W(M,r,cb) = m;
    }
    __syncthreads();

    // byte-packed vertical OR into TU from M
#define VPASS_U(R0, NR, CB0, NC)                                              \
    for (int i = tid; i < (NR)*(NC); i += 256) {                              \
        int q = i/(NC); int r = (R0)+q; int cb = (CB0) + 4*(i - q*(NC));      \
        U32W(TU,r,cb) = U32(M,r-2,cb)|U32(M,r-1,cb)|U32(M,r,cb)               \
                       |U32(M,r+1,cb)|U32(M,r+2,cb);                          \
    }

    // horizontal byte OR over sc-2..sc+2 of TU  (little-endian byte lanes)
#define HOR_U(r, cb, any)                                                     \
    unsigned pv = U32(TU,r,cb-4), md = U32(TU,r,cb), nx = U32(TU,r,cb+4);     \
    unsigned any = md | __funnelshift_r(md,nx,8) | __funnelshift_r(md,nx,16)  \
                      | __funnelshift_l(pv,md,8) | __funnelshift_l(pv,md,16);

    // suppression stage: SMK = any, SS = any? 0 : sT
#define SUPP(R0, NR, CB0, NC)                                                 \
    for (int i = tid; i < (NR)*(NC); i += 256) {                              \
        int q = i/(NC); int r = (R0)+q; int cb = (CB0) + 4*(i - q*(NC));      \
        HOR_U(r, cb, any)                                                     \
        U32W(SMK,r,cb) = any;                                                 \
        float4 t = F4(sT,r,cb); float4 ss;                                    \
        ss.x = (any & 0xFFu)        ? 0.f : t.x;                              \
        ss.y = (any & 0xFF00u)      ? 0.f : t.y;                              \
        ss.z = (any & 0xFF0000u)    ? 0.f : t.z;                              \
        ss.w = (any & 0xFF000000u)  ? 0.f : t.w;                              \
        F4W(SS,r,cb) = ss;                                                    \
    }

    // ---- stage 2 ----
    VPASS_U(4, 44, 4, 12)
    __syncthreads();
    SUPP(4, 44, 4, 12)
    __syncthreads();

    // ---- stage 3: M |= (SS == max5(SS)) & !SMK ----
    VPASS_F(SS, 6, 40, 4, 12)
    __syncthreads();
    for (int i = tid; i < 40*10; i += 256) {        // rows [6,46), sc [8,48)
        int q = i/10; int r = 6+q; int cb = 8 + 4*(i - q*10);
        HWIN(r, cb, o0, o1, o2, o3)
        float4 ss = F4(SS,r,cb);
        unsigned sm = U32(SMK,r,cb);
        unsigned add = 0;
        if (ss.x==o0 && !(sm & 0xFFu))       add |= 1u;
        if (ss.y==o1 && !(sm & 0xFF00u))     add |= 0x100u;
        if (ss.z==o2 && !(sm & 0xFF0000u))   add |= 0x10000u;
        if (ss.w==o3 && !(sm & 0xFF000000u)) add |= 0x1000000u;
        if (add) U32W(M,r,cb) = U32(M,r,cb) | add;
    }
    __syncthreads();

    // ---- stage 4 ----
    VPASS_U(8, 36, 8, 10)
    __syncthreads();
    SUPP(8, 36, 8, 10)
    __syncthreads();

    // ---- stage 5 + border + compaction ----
    VPASS_F(SS, 10, 32, 8, 10)
    __syncthreads();
    for (int i = tid; i < 32*8; i += 256) {         // rows [10,42), sc [12,44)
        int q = i/8; int r = 10+q; int cb = 12 + 4*(i - q*8);
        HWIN(r, cb, o0, o1, o2, o3)
        float4 ss = F4(SS,r,cb);
        unsigned sm = U32(SMK,r,cb);
        unsigned mm = U32(M,r,cb);
        float om[4] = {o0, o1, o2, o3};
        float sv[4] = {ss.x, ss.y, ss.z, ss.w};
        #pragma unroll
        for (int j = 0; j < 4; j++) {
            int fin = ((mm >> (8*j)) & 0xFFu)
                    | ((sv[j] == om[j]) && !((sm >> (8*j)) & 0xFFu));
            if (fin) {
                int gy = gy0 + r, gx = gx0 + cb + j - 2;
                if (gy >= 3 && gy < H-2 && gx >= 3 && gx < W-2) {
                    int pos = atomicAdd(&g_cnt[b], 1);
                    if (pos < CAP) {
                        g_cval[b*CAP + pos] = sT[r*WP + cb + j];
                        g_cidx[b*CAP + pos] = gy*W + gx;
                    }
                }
            }
        }
    }
}

// ============================================================================
// per-batch top-500: 3-level radix threshold (warp-hierarchical bin find)
// + O(cnt) rank placement (no sort)
// ============================================================================
__global__ __launch_bounds__(1024) void select_kernel() {
    __shared__ unsigned hist[2048];
    __shared__ unsigned gsum[64];
    __shared__ unsigned sel_key[1024];
    __shared__ int      sel_idx[1024];
    __shared__ int s_bsel, s_need, s_cnt;

    int b = blockIdx.x, tid = threadIdx.x;
    int lane = tid & 31, wid = tid >> 5;
    int n = min(g_cnt[b], CAP);
    const float* vals = g_cval + b*CAP;
    const int*   idxs = g_cidx + b*CAP;

    unsigned prefix = 0;
    int need = TOPK;
    for (int level = 0; level < 3; level++) {
        int nbins = (level == 2) ? 1024 : 2048;
        for (int i = tid; i < nbins; i += 1024) hist[i] = 0;
        __syncthreads();
        for (int i = tid; i < n; i += 1024) {
            unsigned key = __float_as_uint(vals[i]);
            unsigned bin; bool ok;
            if (level == 0)      { ok = true;                  bin = key >> 21; }
            else if (level == 1) { ok = (key >> 21) == prefix; bin = (key >> 10) & 0x7FF; }
            else                 { ok = (key >> 10) == prefix; bin = key & 0x3FF; }
            if (ok) atomicAdd(&hist[bin], 1);
        }
        __syncthreads();
        // group sums: warp w owns bins [w*32,(w+1)*32)
        {
            unsigned v = hist[tid];
            #pragma unroll
            for (int o = 16; o > 0; o >>= 1) v += __shfl_down_sync(~0u, v, o);
            if (lane == 0) gsum[wid] = v;
            if (nbins == 2048) {
                unsigned v2 = hist[tid + 1024];
                #pragma unroll
                for (int o = 16; o > 0; o >>= 1) v2 += __shfl_down_sync(~0u, v2, o);
                if (lane == 0) gsum[32 + wid] = v2;
            }
        }
        __syncthreads();
        if (wid == 0) {
            int ng = nbins >> 5;                 // 64 or 32 groups
            unsigned g0 = gsum[lane];
            unsigned g1 = (ng == 64) ? gsum[32 + lane] : 0u;
            unsigned s1 = g1;
            #pragma unroll
            for (int o = 1; o < 32; o <<= 1) { unsigned t = __shfl_down_sync(~0u, s1, o); if (lane + o < 32) s1 += t; }
            unsigned tot1 = __shfl_sync(~0u, s1, 0);
            unsigned s0 = g0;
            #pragma unroll
            for (int o = 1; o < 32; o <<= 1) { unsigned t = __shfl_down_sync(~0u, s0, o); if (lane + o < 32) s0 += t; }
            s0 += tot1;                          // suffix including upper groups
            unsigned b0 = __ballot_sync(~0u, s0 >= (unsigned)need);
            unsigned b1 = __ballot_sync(~0u, (ng == 64) && (s1 >= (unsigned)need));
            int gstar;
            unsigned suf_after;
            if (b1) {
                int j = 31 - __clz(b1);
                gstar = 32 + j;
                suf_after = (j == 31) ? 0u : __shfl_sync(~0u, s1, j + 1);
            } else {
                gstar = 31 - __clz(b0);
                suf_after = (gstar == 31) ? tot1 : __shfl_sync(~0u, s0, gstar + 1);
            }
            int need_g = need - (int)suf_after;
            unsigned hs = hist[gstar*32 + lane];
            #pragma unroll
            for (int o = 1; o < 32; o <<= 1) { unsigned t = __shfl_down_sync(~0u, hs, o); if (lane + o < 32) hs += t; }
            unsigned bb = __ballot_sync(~0u, hs >= (unsigned)need_g);
            int bstar = 31 - __clz(bb);
            unsigned bsuf = (bstar == 31) ? 0u : __shfl_sync(~0u, hs, bstar + 1);
            if (lane == 0) { s_bsel = gstar*32 + bstar; s_need = need_g - (int)bsuf; }
        }
        __syncthreads();
        if (level == 0)      prefix = (unsigned)s_bsel;
        else if (level == 1) prefix = (prefix << 11) | (unsigned)s_bsel;
        else                 prefix = (prefix << 10) | (unsigned)s_bsel;
        need = s_need;
        __syncthreads();
    }
    unsigned T = prefix;   // exact 500th-largest key

    if (tid == 0) s_cnt = 0;
    __syncthreads();
    for (int i = tid; i < n; i += 1024) {
        unsigned key = __float_as_uint(vals[i]);
        if (key >= T) {
            int p = atomicAdd(&s_cnt, 1);
            if (p < 1024) { sel_key[p] = key; sel_idx[p] = idxs[i]; }
        }
    }
    __syncthreads();
    int cnt = min(s_cnt, 1024);
    // rank placement: strict total order (key desc, idx asc) -> unique ranks
    if (tid < cnt) {
        unsigned ki = sel_key[tid];
        int ii = sel_idx[tid];
        int rank = 0;
        for (int j = 0; j < cnt; j++) {
            unsigned kj = sel_key[j];
            int ij = sel_idx[j];
            rank += (kj > ki) || (kj == ki && ij < ii);
        }
        if (rank < TOPK) g_topk[b*TOPK + rank] = ii;
    }
}

__device__ __forceinline__ float wmax(float v) {
    #pragma unroll
    for (int o = 16; o > 0; o >>= 1) v = fmaxf(v, __shfl_xor_sync(0xffffffffu, v, o));
    return v;
}

// one warp per keypoint: 5x5 patch softmax refinement (fused moments)
__global__ void patch_kernel(const float* __restrict__ s, float* __restrict__ out) {
    int gw = blockIdx.x * (blockDim.x >> 5) + (threadIdx.x >> 5);
    if (gw >= NKP) return;
    int lane = threadIdx.x & 31;
    int b = gw / TOPK;
    int p = g_topk[gw];
    int y = p / W, x = p - y*W;

    int ky = lane / 5, kx = lane - ky*5;
    float v = -FLT_MAX;
    if (lane < 25) v = s[(size_t)b*HW + (y + ky - 2)*W + (x + kx - 2)];
    float mx = wmax(v);
    float gxk = (float)(kx - 2), gyk = (float)(ky - 2);
    float e = (lane < 25) ? __expf((v - mx) * 10.f) : 0.f;
    float s0 = e, s1 = e*gxk, s2 = e*gyk, s3 = e*(gxk*gxk + gyk*gyk);
    #pragma unroll
    for (int o = 16; o > 0; o >>= 1) {
        s0 += __shfl_xor_sync(~0u, s0, o);
        s1 += __shfl_xor_sync(~0u, s1, o);
        s2 += __shfl_xor_sync(~0u, s2, o);
        s3 += __shfl_xor_sync(~0u, s3, o);
    }

    if (lane == 0) {
        float denom = s0 + 1e-12f;
        float inv = 1.f / denom;
        float xr = s1 * inv, yr = s2 * inv;
        float disp = (s3 - 2.f*xr*s1 - 2.f*yr*s2 + (xr*xr + yr*yr)*s0) * 0.25f * inv;

        float fx = (float)x + xr, fy = (float)y + yr;
        float gx = fx / (float)(W-1) * 2.f - 1.f;
        float gy = fy / (float)(H-1) * 2.f - 1.f;
        out[KXY_OFF + gw*2 + 0] = gx;
        out[KXY_OFF + gw*2 + 1] = gy;
        out[DISP_OFF + gw] = disp;

        float px = fminf(fmaxf((gx + 1.f) * 0.5f * (float)(W-1), 0.f), (float)(W-1));
        float py = fminf(fmaxf((gy + 1.f) * 0.5f * (float)(H-1), 0.f), (float)(H-1));
        g_px[gw] = px; g_py[gw] = py;
        int x0 = (int)floorf(px), y0 = (int)floorf(py);
        float wx = px - (float)x0, wy = py - (float)y0;
        int x1 = min(x0 + 1, W-1), y1 = min(y0 + 1, H-1);
        const float* sb = s + (size_t)b*HW;
        float v00 = sb[y0*W + x0], v01 = sb[y0*W + x1];
        float v10 = sb[y1*W + x0], v11 = sb[y1*W + x1];
        out[KPS_OFF + gw] = v00*(1.f-wx)*(1.f-wy) + v01*wx*(1.f-wy)
                          + v10*(1.f-wx)*wy       + v11*wx*wy;
    }
}

// 64 threads per keypoint: descriptor bilinear gather + L2 normalize
__global__ void desc_kernel(const float* __restrict__ dmap, float* __restrict__ out) {
    int g = blockIdx.x * 4 + (threadIdx.x >> 6);
    int c = threadIdx.x & 63;
    if (g >= NKP) return;
    float px = g_px[g], py = g_py[g];
    int x0 = (int)floorf(px), y0 = (int)floorf(py);
    float wx = px - (float)x0, wy = py - (float)y0;
    int x1 = min(x0 + 1, W-1), y1 = min(y0 + 1, H-1);
    int b = g / TOPK;
    const float* base = dmap + ((size_t)b*64 + c) * (size_t)HW;
    float v00 = base[y0*W + x0], v01 = base[y0*W + x1];
    float v10 = base[y1*W + x0], v11 = base[y1*W + x1];
    float d = v00*(1.f-wx)*(1.f-wy) + v01*wx*(1.f-wy)
            + v10*(1.f-wx)*wy       + v11*wx*wy;

    float ss = d * d;
    #pragma unroll
    for (int o = 16; o > 0; o >>= 1) ss += __shfl_xor_sync(0xffffffffu, ss, o);
    __shared__ float part[8];
    int wid = threadIdx.x >> 5;
    if ((threadIdx.x & 31) == 0) part[wid] = ss;
    __syncthreads();
    int gl = threadIdx.x >> 6;
    float tot = part[2*gl] + part[2*gl + 1];
    float nrm = fmaxf(sqrtf(tot), 1e-12f);
    out[DESC_OFF + g*64 + c] = d / nrm;
}

extern "C" void kernel_launch(void* const* d_in, const int* in_sizes, int n_in,
                              void* d_out, int out_size) {
    const float* scores = (const float*)d_in[0];
    const float* descs  = (const float*)d_in[1];
    float* out = (float*)d_out;

    zero_cnt_kernel<<<1, 32>>>();
    nms_kernel<<<dim3(W/32, H/32, B), 256>>>(scores);
    select_kernel<<<B, 1024>>>();
    patch_kernel<<<(NKP*32 + 255)/256, 256>>>(scores, out);
    desc_kernel<<<NKP/4, 256>>>(descs, out);
}